// round 16
// baseline (speedup 1.0000x reference)
#include <cuda_runtime.h>
#include <math.h>

#define N_NODES 100000
#define N_EDGES 1600000
#define IN_DIM  64
#define EMB     128
#define ED      32

#define SCAN_BLK 512
#define NBLK ((N_NODES + SCAN_BLK - 1) / SCAN_BLK)   // 196

typedef unsigned long long u64;
typedef unsigned int u32;

__device__ __forceinline__ u32 to_tf32(float f) {
    u32 r; asm("cvt.rna.tf32.f32 %0, %1;" : "=r"(r) : "f"(f)); return r;
}
__device__ __forceinline__ void mma_tf32(float c[4], const u32 a[4], const u32 b[2]) {
    asm volatile(
        "mma.sync.aligned.m16n8k8.row.col.f32.tf32.tf32.f32 "
        "{%0,%1,%2,%3}, {%4,%5,%6,%7}, {%8,%9}, {%0,%1,%2,%3};"
        : "+f"(c[0]), "+f"(c[1]), "+f"(c[2]), "+f"(c[3])
        : "r"(a[0]), "r"(a[1]), "r"(a[2]), "r"(a[3]), "r"(b[0]), "r"(b[1]));
}

__device__ float g_agg[2][(size_t)N_NODES * IN_DIM];
__device__ float g_t[2][(size_t)N_NODES * EMB];

// CSR scratch
__device__ int  g_deg[2][N_NODES];
__device__ int  g_cur[2][N_NODES];
__device__ int  g_off[2][N_NODES + 1];
__device__ int  g_partial[2][NBLK];
__device__ int  g_pscan[2][NBLK];
__device__ int2 g_elist2[2][N_EDGES];   // {edge id, gather node}

// ---------------------------------------------------------------------------
// CSR build
// ---------------------------------------------------------------------------
__global__ void zero_deg_kernel() {
    int i = blockIdx.x * blockDim.x + threadIdx.x;
    if (i < N_NODES) { g_deg[0][i] = 0; g_deg[1][i] = 0; }
}

__global__ void count_kernel(const int* __restrict__ ei) {
    int e = blockIdx.x * blockDim.x + threadIdx.x;
    if (e < N_EDGES) {
        int s = ei[e];
        int d = ei[N_EDGES + e];
        atomicAdd(&g_deg[0][d], 1);
        atomicAdd(&g_deg[1][s], 1);
    }
}

__global__ void scan1_kernel() {
    const int dir = blockIdx.y;
    __shared__ int sred[SCAN_BLK];
    int i = blockIdx.x * SCAN_BLK + threadIdx.x;
    sred[threadIdx.x] = (i < N_NODES) ? g_deg[dir][i] : 0;
    __syncthreads();
    for (int ofs = SCAN_BLK / 2; ofs > 0; ofs >>= 1) {
        if (threadIdx.x < ofs) sred[threadIdx.x] += sred[threadIdx.x + ofs];
        __syncthreads();
    }
    if (threadIdx.x == 0) g_partial[dir][blockIdx.x] = sred[0];
}

__global__ void scan2_kernel() {
    const int dir = blockIdx.y;
    __shared__ int sb[2][256];
    int t = threadIdx.x;
    int v = (t < NBLK) ? g_partial[dir][t] : 0;
    sb[0][t] = v;
    __syncthreads();
    int cur = 0;
#pragma unroll
    for (int ofs = 1; ofs < 256; ofs <<= 1) {
        int val = sb[cur][t];
        if (t >= ofs) val += sb[cur][t - ofs];
        sb[cur ^ 1][t] = val;
        __syncthreads();
        cur ^= 1;
    }
    if (t < NBLK) g_pscan[dir][t] = sb[cur][t] - v;
}

__global__ void scan3_kernel() {
    const int dir = blockIdx.y;
    __shared__ int sb[2][SCAN_BLK];
    int t = threadIdx.x;
    int i = blockIdx.x * SCAN_BLK + t;
    int v = (i < N_NODES) ? g_deg[dir][i] : 0;
    sb[0][t] = v;
    __syncthreads();
    int cur = 0;
#pragma unroll
    for (int ofs = 1; ofs < SCAN_BLK; ofs <<= 1) {
        int val = sb[cur][t];
        if (t >= ofs) val += sb[cur][t - ofs];
        sb[cur ^ 1][t] = val;
        __syncthreads();
        cur ^= 1;
    }
    int incl = sb[cur][t];
    int base = g_pscan[dir][blockIdx.x];
    if (i < N_NODES) {
        int excl = base + incl - v;
        g_off[dir][i] = excl;
        g_cur[dir][i] = excl;
        if (i == N_NODES - 1) g_off[dir][N_NODES] = base + incl;
    }
}

__global__ void fill_kernel(const int* __restrict__ ei) {
    int e = blockIdx.x * blockDim.x + threadIdx.x;
    if (e < N_EDGES) {
        int s = ei[e];
        int d = ei[N_EDGES + e];
        int p0 = atomicAdd(&g_cur[0][d], 1);
        g_elist2[0][p0] = make_int2(e, s);
        int p1 = atomicAdd(&g_cur[1][s], 1);
        g_elist2[1][p1] = make_int2(e, d);
    }
}

// ---------------------------------------------------------------------------
// Aggregation via tf32 MMA (R15 proven): warp per node, 16-edge groups.
// ---------------------------------------------------------------------------
__global__ __launch_bounds__(256, 2) void agg_kernel(
    const float2* __restrict__ x2,        // x as [N_NODES][32] float2
    const float* __restrict__ ea,         // [N_EDGES][32]
    const float* __restrict__ We_in,      // [32][64]
    const float2* __restrict__ be_in2,    // [32] float2
    const float* __restrict__ We_out,
    const float2* __restrict__ be_out2)
{
    const int dir  = blockIdx.y;
    const int lane = threadIdx.x & 31;
    const int w    = threadIdx.x >> 5;
    const int tid  = threadIdx.x;

    const float*  We  = dir ? We_out : We_in;
    const float2* be2 = dir ? be_out2 : be_in2;
    const int*  off   = g_off[dir];
    const int2* elist = g_elist2[dir];
    float* __restrict__ agg = g_agg[dir];

    __shared__ u32 sWf[8 * 4 * 32 * 2];          // 8 KB
    __shared__ u32 sEa[8][16][36];               // tf32 ea rows, pad 36
    __shared__ int sIds[8][16];

#pragma unroll
    for (int it = 0; it < 8; it++) {
        int idx = it * 256 + tid;                // 0..2047: kc*64 + n
        int kc = idx >> 6;
        int n  = idx & 63;
        float v = We[kc * 64 + n];
        int k8 = kc >> 3, kk = kc & 7;
        int tg = kk & 3, slot = kk >> 2;
        int nt = n >> 3, gg = n & 7;
        sWf[((nt * 4 + k8) * 32 + gg * 4 + tg) * 2 + slot] = to_tf32(v);
    }
    __syncthreads();

    const int g   = lane >> 2;       // 0..7
    const int tig = lane & 3;        // 0..3
    const int row  = lane >> 1;      // staging row 0..15
    const int part = lane & 1;       // staging half

    float2 bp[8];
#pragma unroll
    for (int nt = 0; nt < 8; nt++) bp[nt] = be2[nt * 4 + tig];

    const int warpGlobal = blockIdx.x * 8 + w;
    const int nwarps = gridDim.x * 8;

    for (int nd = warpGlobal; nd < N_NODES; nd += nwarps) {
        const int beg = off[nd];
        const int end = off[nd + 1];

        float2 accN[8];
#pragma unroll
        for (int nt = 0; nt < 8; nt++) accN[nt] = make_float2(0.f, 0.f);

        for (int j0 = beg; j0 < end; j0 += 16) {
            int slot = min(j0 + row, end - 1);
            int2 pr = elist[slot];
            if (part == 0) sIds[w][row] = pr.y;
            const float4* earow = (const float4*)(ea + (size_t)pr.x * 32);
#pragma unroll
            for (int t = 0; t < 4; t++) {
                float4 e4 = earow[part * 4 + t];
                u32* dst = &sEa[w][row][part * 16 + t * 4];
                dst[0] = to_tf32(e4.x);
                dst[1] = to_tf32(e4.y);
                dst[2] = to_tf32(e4.z);
                dst[3] = to_tf32(e4.w);
            }
            __syncwarp();

            int srcA = sIds[w][g];
            int srcB = sIds[w][g + 8];
            const bool vA = (j0 + g < end);
            const bool vB = (j0 + g + 8 < end);

#pragma unroll
            for (int h = 0; h < 2; h++) {
                float2 xa[4], xb[4];
#pragma unroll
                for (int nn = 0; nn < 4; nn++) {
                    int nt = h * 4 + nn;
                    xa[nn] = x2[(size_t)srcA * 32 + nt * 4 + tig];
                    xb[nn] = x2[(size_t)srcB * 32 + nt * 4 + tig];
                }

                float c[4][4];
#pragma unroll
                for (int nn = 0; nn < 4; nn++)
#pragma unroll
                    for (int q = 0; q < 4; q++) c[nn][q] = 0.f;

#pragma unroll
                for (int k8 = 0; k8 < 4; k8++) {
                    u32 a[4];
                    a[0] = sEa[w][g][k8 * 8 + tig];
                    a[1] = sEa[w][g + 8][k8 * 8 + tig];
                    a[2] = sEa[w][g][k8 * 8 + 4 + tig];
                    a[3] = sEa[w][g + 8][k8 * 8 + 4 + tig];
#pragma unroll
                    for (int nn = 0; nn < 4; nn++) {
                        int nt = h * 4 + nn;
                        u32 b[2];
                        *(uint2*)b = *(const uint2*)&sWf[((nt * 4 + k8) * 32 + lane) * 2];
                        mma_tf32(c[nn], a, b);
                    }
                }

#pragma unroll
                for (int nn = 0; nn < 4; nn++) {
                    int nt = h * 4 + nn;
                    float m0 = c[nn][0] + xa[nn].x + bp[nt].x;
                    float m1 = c[nn][1] + xa[nn].y + bp[nt].y;
                    float m2 = c[nn][2] + xb[nn].x + bp[nt].x;
                    float m3 = c[nn][3] + xb[nn].y + bp[nt].y;
                    m0 = fmaxf(m0, 0.f); m1 = fmaxf(m1, 0.f);
                    m2 = fmaxf(m2, 0.f); m3 = fmaxf(m3, 0.f);
                    if (!vA) { m0 = 0.f; m1 = 0.f; }
                    if (!vB) { m2 = 0.f; m3 = 0.f; }
                    float s0 = m0 + m2;
                    float s1 = m1 + m3;
                    s0 += __shfl_xor_sync(0xffffffffu, s0, 4);
                    s1 += __shfl_xor_sync(0xffffffffu, s1, 4);
                    s0 += __shfl_xor_sync(0xffffffffu, s0, 8);
                    s1 += __shfl_xor_sync(0xffffffffu, s1, 8);
                    s0 += __shfl_xor_sync(0xffffffffu, s0, 16);
                    s1 += __shfl_xor_sync(0xffffffffu, s1, 16);
                    accN[nt].x += s0;
                    accN[nt].y += s1;
                }
            }
            __syncwarp();
        }
        *(float2*)&agg[(size_t)nd * 64 + g * 8 + tig * 2] = accN[g];
    }
}

__device__ __forceinline__ float gelu_exact(float v) {
    return 0.5f * v * (1.f + erff(v * 0.70710678118654752f));
}

// ---------------------------------------------------------------------------
// N1 via tf32 mma: t[dir] = gelu((x + agg[dir]) @ W1 + b1)
// Same fragment-major staging as n2; 2 K-chunks of 32.
// ---------------------------------------------------------------------------
__global__ __launch_bounds__(256, 2) void n1_kernel(
    const float* __restrict__ x,
    const float* __restrict__ W1_in,  const float* __restrict__ b1_in,
    const float* __restrict__ W1_out, const float* __restrict__ b1_out)
{
    __shared__ u32 sAf[8 * 4 * 32 * 4];    // 16 KB
    __shared__ u32 sWf[16 * 4 * 32 * 2];   // 16 KB

    const int dir = blockIdx.y;
    const float* W1 = dir ? W1_out : W1_in;
    const float* b1 = dir ? b1_out : b1_in;
    const float* agg = g_agg[dir];
    float* tptr = g_t[dir];

    const int tid  = threadIdx.x;
    const int lane = tid & 31;
    const int warp = tid >> 5;
    const int mw   = warp >> 1;
    const int nw   = warp & 1;
    const int m0   = blockIdx.x * 128;

    float acc[2][8][4];
#pragma unroll
    for (int m = 0; m < 2; m++)
#pragma unroll
        for (int n = 0; n < 8; n++)
#pragma unroll
            for (int q = 0; q < 4; q++) acc[m][n][q] = 0.f;

    const float4* X4 = (const float4*)x;
    const float4* G4 = (const float4*)agg;

#pragma unroll 1
    for (int c = 0; c < 2; c++) {
        const int k4b = c * 8;
        const float4* W4 = (const float4*)W1 + (size_t)c * 32 * 32;

        // ---- stage A = x + agg (128 x 32) into fragment-major tf32 ----
#pragma unroll
        for (int it = 0; it < 4; it++) {
            int idx = it * 256 + tid;
            int r   = idx >> 3;
            int q   = idx & 7;
            float4 v = make_float4(0.f, 0.f, 0.f, 0.f);
            int gr = m0 + r;
            if (gr < N_NODES) {
                float4 xv = X4[(size_t)gr * 16 + k4b + q];
                float4 gv = G4[(size_t)gr * 16 + k4b + q];
                v.x = xv.x + gv.x; v.y = xv.y + gv.y;
                v.z = xv.z + gv.z; v.w = xv.w + gv.w;
            }
            int mt = r >> 4, rr = r & 15;
            int gg = rr & 7, slr = rr >> 3;
            int k8 = q >> 1, slc = q & 1;
            int slot = slr + 2 * slc;
            u32* base = &sAf[(mt * 4 + k8) * 128 + gg * 4 * 4 + slot];
            base[0 * 4] = to_tf32(v.x);
            base[1 * 4] = to_tf32(v.y);
            base[2 * 4] = to_tf32(v.z);
            base[3 * 4] = to_tf32(v.w);
        }
        // ---- stage W chunk (32 x 128) ----
#pragma unroll
        for (int it = 0; it < 4; it++) {
            int idx = it * 256 + tid;
            int kc  = idx >> 5;
            int n4  = idx & 31;
            float4 wv = W4[kc * 32 + n4];
            int k8 = kc >> 3, kk = kc & 7;
            int tg = kk & 3, slot = kk >> 2;
            float wf[4] = { wv.x, wv.y, wv.z, wv.w };
#pragma unroll
            for (int e = 0; e < 4; e++) {
                int n  = n4 * 4 + e;
                int nt = n >> 3, gg = n & 7;
                sWf[((nt * 4 + k8) * 32 + gg * 4 + tg) * 2 + slot] = to_tf32(wf[e]);
            }
        }
        __syncthreads();

#pragma unroll
        for (int k8 = 0; k8 < 4; k8++) {
            u32 af[2][4];
#pragma unroll
            for (int m = 0; m < 2; m++)
                *(uint4*)af[m] = *(const uint4*)&sAf[((mw * 2 + m) * 4 + k8) * 128 + lane * 4];
#pragma unroll
            for (int n = 0; n < 8; n++) {
                int nt = nw * 8 + n;
                u32 b[2];
                *(uint2*)b = *(const uint2*)&sWf[((nt * 4 + k8) * 32 + lane) * 2];
                mma_tf32(acc[0][n], af[0], b);
                mma_tf32(acc[1][n], af[1], b);
            }
        }
        __syncthreads();
    }

    // ---- epilogue: gelu + store ----
    const int gg  = lane >> 2;
    const int tg  = lane & 3;
#pragma unroll
    for (int m = 0; m < 2; m++) {
        int row  = m0 + (mw * 2 + m) * 16 + gg;
        int row2 = row + 8;
#pragma unroll
        for (int n = 0; n < 8; n++) {
            int col = nw * 64 + n * 8 + tg * 2;
            float b0 = b1[col];
            float b1v = b1[col + 1];
            if (row < N_NODES) {
                float2 o = make_float2(gelu_exact(acc[m][n][0] + b0),
                                       gelu_exact(acc[m][n][1] + b1v));
                *(float2*)&tptr[(size_t)row * EMB + col] = o;
            }
            if (row2 < N_NODES) {
                float2 o = make_float2(gelu_exact(acc[m][n][2] + b0),
                                       gelu_exact(acc[m][n][3] + b1v));
                *(float2*)&tptr[(size_t)row2 * EMB + col] = o;
            }
        }
    }
}

// ---------------------------------------------------------------------------
// N2 via tf32 mma.m16n8k8 (validated in R14).
// ---------------------------------------------------------------------------
__global__ __launch_bounds__(256, 2) void n2_kernel(
    const float* __restrict__ x,
    const float* __restrict__ W2_in,  const float* __restrict__ b2_in,
    const float* __restrict__ W2_out, const float* __restrict__ b2_out,
    const float* __restrict__ Wr,     const float* __restrict__ br,
    float* __restrict__ out)
{
    __shared__ u32 sAf[8 * 4 * 32 * 4];    // 16 KB
    __shared__ u32 sWf[16 * 4 * 32 * 2];   // 16 KB

    const int tid  = threadIdx.x;
    const int lane = tid & 31;
    const int warp = tid >> 5;
    const int mw   = warp >> 1;
    const int nw   = warp & 1;
    const int m0   = blockIdx.x * 128;

    float acc[2][8][4];
#pragma unroll
    for (int m = 0; m < 2; m++)
#pragma unroll
        for (int n = 0; n < 8; n++)
#pragma unroll
            for (int q = 0; q < 4; q++) acc[m][n][q] = 0.f;

#pragma unroll 1
    for (int c = 0; c < 10; c++) {
        const float4* A4; int lda4, k4b; const float4* W4; float scale;
        if (c < 4)      { A4 = (const float4*)g_t[1]; lda4 = 32; k4b = c * 8;
                          W4 = (const float4*)W2_out + (size_t)c * 32 * 32; scale = 0.5f; }
        else if (c < 8) { A4 = (const float4*)g_t[0]; lda4 = 32; k4b = (c - 4) * 8;
                          W4 = (const float4*)W2_in + (size_t)(c - 4) * 32 * 32; scale = 0.5f; }
        else            { A4 = (const float4*)x;      lda4 = 16; k4b = (c - 8) * 8;
                          W4 = (const float4*)Wr + (size_t)(c - 8) * 32 * 32; scale = 1.f; }

#pragma unroll
        for (int it = 0; it < 4; it++) {
            int idx = it * 256 + tid;
            int r   = idx >> 3;
            int q   = idx & 7;
            float4 v = make_float4(0.f, 0.f, 0.f, 0.f);
            int gr = m0 + r;
            if (gr < N_NODES) {
                v = A4[(size_t)gr * lda4 + k4b + q];
                v.x *= scale; v.y *= scale; v.z *= scale; v.w *= scale;
            }
            int mt = r >> 4, rr = r & 15;
            int gg = rr & 7, slr = rr >> 3;
            int k8 = q >> 1, slc = q & 1;
            int slot = slr + 2 * slc;
            u32* base = &sAf[(mt * 4 + k8) * 128 + gg * 4 * 4 + slot];
            base[0 * 4] = to_tf32(v.x);
            base[1 * 4] = to_tf32(v.y);
            base[2 * 4] = to_tf32(v.z);
            base[3 * 4] = to_tf32(v.w);
        }
#pragma unroll
        for (int it = 0; it < 4; it++) {
            int idx = it * 256 + tid;
            int kc  = idx >> 5;
            int n4  = idx & 31;
            float4 wv = W4[kc * 32 + n4];
            int k8 = kc >> 3, kk = kc & 7;
            int tg = kk & 3, slot = kk >> 2;
            float wf[4] = { wv.x, wv.y, wv.z, wv.w };
#pragma unroll
            for (int e = 0; e < 4; e++) {
                int n  = n4 * 4 + e;
                int nt = n >> 3, gg = n & 7;
                sWf[((nt * 4 + k8) * 32 + gg * 4 + tg) * 2 + slot] = to_tf32(wf[e]);
            }
        }
        __syncthreads();

#pragma unroll
        for (int k8 = 0; k8 < 4; k8++) {
            u32 af[2][4];
#pragma unroll
            for (int m = 0; m < 2; m++)
                *(uint4*)af[m] = *(const uint4*)&sAf[((mw * 2 + m) * 4 + k8) * 128 + lane * 4];
#pragma unroll
            for (int n = 0; n < 8; n++) {
                int nt = nw * 8 + n;
                u32 b[2];
                *(uint2*)b = *(const uint2*)&sWf[((nt * 4 + k8) * 32 + lane) * 2];
                mma_tf32(acc[0][n], af[0], b);
                mma_tf32(acc[1][n], af[1], b);
            }
        }
        __syncthreads();
    }

    const int gg  = lane >> 2;
    const int tg  = lane & 3;
#pragma unroll
    for (int m = 0; m < 2; m++) {
        int row  = m0 + (mw * 2 + m) * 16 + gg;
        int row2 = row + 8;
#pragma unroll
        for (int n = 0; n < 8; n++) {
            int col = nw * 64 + n * 8 + tg * 2;
            float bias0 = 0.5f * (b2_out[col] + b2_in[col]) + br[col];
            float bias1 = 0.5f * (b2_out[col + 1] + b2_in[col + 1]) + br[col + 1];
            if (row < N_NODES) {
                float2 o = make_float2(acc[m][n][0] + bias0, acc[m][n][1] + bias1);
                *(float2*)&out[(size_t)row * EMB + col] = o;
            }
            if (row2 < N_NODES) {
                float2 o = make_float2(acc[m][n][2] + bias0, acc[m][n][3] + bias1);
                *(float2*)&out[(size_t)row2 * EMB + col] = o;
            }
        }
    }
}

// ---------------------------------------------------------------------------
// launch
// ---------------------------------------------------------------------------
extern "C" void kernel_launch(void* const* d_in, const int* in_sizes, int n_in,
                              void* d_out, int out_size)
{
    const float* x      = (const float*)d_in[0];
    const int*   ei     = (const int*)d_in[1];
    const float* ea     = (const float*)d_in[2];
    const float* We_in  = (const float*)d_in[3];
    const float* be_in  = (const float*)d_in[4];
    const float* W1_in  = (const float*)d_in[5];
    const float* b1_in  = (const float*)d_in[6];
    const float* W2_in  = (const float*)d_in[7];
    const float* b2_in  = (const float*)d_in[8];
    const float* We_out = (const float*)d_in[9];
    const float* be_out = (const float*)d_in[10];
    const float* W1_out = (const float*)d_in[11];
    const float* b1_out = (const float*)d_in[12];
    const float* W2_out = (const float*)d_in[13];
    const float* b2_out = (const float*)d_in[14];
    const float* Wr     = (const float*)d_in[15];
    const float* br     = (const float*)d_in[16];
    float* out = (float*)d_out;

    // ---- CSR build ----
    zero_deg_kernel<<<(N_NODES + 255) / 256, 256>>>();
    count_kernel<<<(N_EDGES + 255) / 256, 256>>>(ei);
    scan1_kernel<<<dim3(NBLK, 2), SCAN_BLK>>>();
    scan2_kernel<<<dim3(1, 2), 256>>>();
    scan3_kernel<<<dim3(NBLK, 2), SCAN_BLK>>>();
    fill_kernel<<<(N_EDGES + 255) / 256, 256>>>(ei);

    // ---- aggregation (tf32 mma) ----
    agg_kernel<<<dim3(296, 2), 256>>>(
        (const float2*)x, ea,
        We_in,  (const float2*)be_in,
        We_out, (const float2*)be_out);

    // ---- node MLPs (tf32 mma) ----
    dim3 ngrid((N_NODES + 127) / 128, 2);
    n1_kernel<<<ngrid, 256>>>(x, W1_in, b1_in, W1_out, b1_out);

    n2_kernel<<<(N_NODES + 127) / 128, 256>>>(
        x, W2_in, b2_in, W2_out, b2_out, Wr, br, out);
}

// round 17
// speedup vs baseline: 1.0142x; 1.0142x over previous
#include <cuda_runtime.h>
#include <math.h>

#define N_NODES 100000
#define N_EDGES 1600000
#define IN_DIM  64
#define EMB     128
#define ED      32

#define SCAN_BLK 512
#define NBLK ((N_NODES + SCAN_BLK - 1) / SCAN_BLK)   // 196

typedef unsigned long long u64;
typedef unsigned int u32;

__device__ __forceinline__ u64 pack2(float x, float y) {
    u64 r; asm("mov.b64 %0, {%1, %2};" : "=l"(r) : "f"(x), "f"(y)); return r;
}
__device__ __forceinline__ void unpack2(u64 v, float& x, float& y) {
    asm("mov.b64 {%0, %1}, %2;" : "=f"(x), "=f"(y) : "l"(v));
}
__device__ __forceinline__ u64 ffma2(u64 a, u64 b, u64 c) {
    u64 d; asm("fma.rn.f32x2 %0, %1, %2, %3;" : "=l"(d) : "l"(a), "l"(b), "l"(c));
    return d;
}
__device__ __forceinline__ u32 to_tf32(float f) {
    u32 r; asm("cvt.rna.tf32.f32 %0, %1;" : "=r"(r) : "f"(f)); return r;
}
__device__ __forceinline__ void mma_tf32(float c[4], const u32 a[4], const u32 b[2]) {
    asm volatile(
        "mma.sync.aligned.m16n8k8.row.col.f32.tf32.tf32.f32 "
        "{%0,%1,%2,%3}, {%4,%5,%6,%7}, {%8,%9}, {%0,%1,%2,%3};"
        : "+f"(c[0]), "+f"(c[1]), "+f"(c[2]), "+f"(c[3])
        : "r"(a[0]), "r"(a[1]), "r"(a[2]), "r"(a[3]), "r"(b[0]), "r"(b[1]));
}

__device__ float g_agg[2][(size_t)N_NODES * IN_DIM];
__device__ float g_t[2][(size_t)N_NODES * EMB];

// CSR scratch
__device__ int  g_deg[2][N_NODES];
__device__ int  g_cur[2][N_NODES];
__device__ int  g_off[2][N_NODES + 1];
__device__ int  g_partial[2][NBLK];
__device__ int  g_pscan[2][NBLK];
__device__ int2 g_elist2[2][N_EDGES];   // {edge id, gather node}

// ---------------------------------------------------------------------------
// CSR build
// ---------------------------------------------------------------------------
__global__ void zero_deg_kernel() {
    int i = blockIdx.x * blockDim.x + threadIdx.x;
    if (i < N_NODES) { g_deg[0][i] = 0; g_deg[1][i] = 0; }
}

__global__ void count_kernel(const int* __restrict__ ei) {
    int e = blockIdx.x * blockDim.x + threadIdx.x;
    if (e < N_EDGES) {
        int s = ei[e];
        int d = ei[N_EDGES + e];
        atomicAdd(&g_deg[0][d], 1);
        atomicAdd(&g_deg[1][s], 1);
    }
}

__global__ void scan1_kernel() {
    const int dir = blockIdx.y;
    __shared__ int sred[SCAN_BLK];
    int i = blockIdx.x * SCAN_BLK + threadIdx.x;
    sred[threadIdx.x] = (i < N_NODES) ? g_deg[dir][i] : 0;
    __syncthreads();
    for (int ofs = SCAN_BLK / 2; ofs > 0; ofs >>= 1) {
        if (threadIdx.x < ofs) sred[threadIdx.x] += sred[threadIdx.x + ofs];
        __syncthreads();
    }
    if (threadIdx.x == 0) g_partial[dir][blockIdx.x] = sred[0];
}

__global__ void scan2_kernel() {
    const int dir = blockIdx.y;
    __shared__ int sb[2][256];
    int t = threadIdx.x;
    int v = (t < NBLK) ? g_partial[dir][t] : 0;
    sb[0][t] = v;
    __syncthreads();
    int cur = 0;
#pragma unroll
    for (int ofs = 1; ofs < 256; ofs <<= 1) {
        int val = sb[cur][t];
        if (t >= ofs) val += sb[cur][t - ofs];
        sb[cur ^ 1][t] = val;
        __syncthreads();
        cur ^= 1;
    }
    if (t < NBLK) g_pscan[dir][t] = sb[cur][t] - v;
}

__global__ void scan3_kernel() {
    const int dir = blockIdx.y;
    __shared__ int sb[2][SCAN_BLK];
    int t = threadIdx.x;
    int i = blockIdx.x * SCAN_BLK + t;
    int v = (i < N_NODES) ? g_deg[dir][i] : 0;
    sb[0][t] = v;
    __syncthreads();
    int cur = 0;
#pragma unroll
    for (int ofs = 1; ofs < SCAN_BLK; ofs <<= 1) {
        int val = sb[cur][t];
        if (t >= ofs) val += sb[cur][t - ofs];
        sb[cur ^ 1][t] = val;
        __syncthreads();
        cur ^= 1;
    }
    int incl = sb[cur][t];
    int base = g_pscan[dir][blockIdx.x];
    if (i < N_NODES) {
        int excl = base + incl - v;
        g_off[dir][i] = excl;
        g_cur[dir][i] = excl;
        if (i == N_NODES - 1) g_off[dir][N_NODES] = base + incl;
    }
}

__global__ void fill_kernel(const int* __restrict__ ei) {
    int e = blockIdx.x * blockDim.x + threadIdx.x;
    if (e < N_EDGES) {
        int s = ei[e];
        int d = ei[N_EDGES + e];
        int p0 = atomicAdd(&g_cur[0][d], 1);
        g_elist2[0][p0] = make_int2(e, s);
        int p1 = atomicAdd(&g_cur[1][s], 1);
        g_elist2[1][p1] = make_int2(e, d);
    }
}

// ---------------------------------------------------------------------------
// Aggregation via tf32 MMA, SOFTWARE PIPELINED: double-buffered sEa;
// next group's elist+ea loaded into registers while current group computes.
// Ids distributed via shfl (lane 2g holds staging row g).
// ---------------------------------------------------------------------------
__global__ __launch_bounds__(256, 2) void agg_kernel(
    const float2* __restrict__ x2,        // x as [N_NODES][32] float2
    const float* __restrict__ ea,         // [N_EDGES][32]
    const float* __restrict__ We_in,      // [32][64]
    const float2* __restrict__ be_in2,    // [32] float2
    const float* __restrict__ We_out,
    const float2* __restrict__ be_out2)
{
    const int dir  = blockIdx.y;
    const int lane = threadIdx.x & 31;
    const int w    = threadIdx.x >> 5;
    const int tid  = threadIdx.x;

    const float*  We  = dir ? We_out : We_in;
    const float2* be2 = dir ? be_out2 : be_in2;
    const int*  off   = g_off[dir];
    const int2* elist = g_elist2[dir];
    float* __restrict__ agg = g_agg[dir];

    __shared__ u32 sWf[8 * 4 * 32 * 2];          // 8 KB
    __shared__ u32 sEa[8][2][16][36];            // 36 KB double-buffered

#pragma unroll
    for (int it = 0; it < 8; it++) {
        int idx = it * 256 + tid;                // 0..2047: kc*64 + n
        int kc = idx >> 6;
        int n  = idx & 63;
        float v = We[kc * 64 + n];
        int k8 = kc >> 3, kk = kc & 7;
        int tg = kk & 3, slot = kk >> 2;
        int nt = n >> 3, gg = n & 7;
        sWf[((nt * 4 + k8) * 32 + gg * 4 + tg) * 2 + slot] = to_tf32(v);
    }
    __syncthreads();

    const int g    = lane >> 2;      // 0..7
    const int tig  = lane & 3;       // 0..3
    const int row  = lane >> 1;      // staging row 0..15
    const int part = lane & 1;       // staging half

    float2 bp[8];
#pragma unroll
    for (int nt = 0; nt < 8; nt++) bp[nt] = be2[nt * 4 + tig];

    const int warpGlobal = blockIdx.x * 8 + w;
    const int nwarps = gridDim.x * 8;

    for (int nd = warpGlobal; nd < N_NODES; nd += nwarps) {
        const int beg = off[nd];
        const int end = off[nd + 1];

        float2 accN[8];
#pragma unroll
        for (int nt = 0; nt < 8; nt++) accN[nt] = make_float2(0.f, 0.f);

        if (beg < end) {
            // prologue: load first group into registers
            int2   prc;
            float4 ec[4];
            {
                int slot = min(beg + row, end - 1);
                prc = elist[slot];
                const float4* earow = (const float4*)(ea + (size_t)prc.x * 32);
#pragma unroll
                for (int t = 0; t < 4; t++) ec[t] = earow[part * 4 + t];
            }

            int buf = 0;
            for (int j0 = beg; j0 < end; j0 += 16) {
                // ---- STS current group (tf32, duplicated halves) ----
#pragma unroll
                for (int t = 0; t < 4; t++) {
                    u32* dst = &sEa[w][buf][row][part * 16 + t * 4];
                    dst[0] = to_tf32(ec[t].x);
                    dst[1] = to_tf32(ec[t].y);
                    dst[2] = to_tf32(ec[t].z);
                    dst[3] = to_tf32(ec[t].w);
                }
                // ids via shfl (lane 2r holds staging row r)
                int srcA = __shfl_sync(0xffffffffu, prc.y, 2 * g);
                int srcB = __shfl_sync(0xffffffffu, prc.y, 2 * (g + 8));
                __syncwarp();

                // ---- prefetch next group into registers ----
                const int jn = j0 + 16;
                int2   prn = prc;
                float4 en[4];
                if (jn < end) {
                    int slot = min(jn + row, end - 1);
                    prn = elist[slot];
                    const float4* earow = (const float4*)(ea + (size_t)prn.x * 32);
#pragma unroll
                    for (int t = 0; t < 4; t++) en[t] = earow[part * 4 + t];
                } else {
#pragma unroll
                    for (int t = 0; t < 4; t++) en[t] = ec[t];
                }

                const bool vA = (j0 + g < end);
                const bool vB = (j0 + g + 8 < end);

#pragma unroll
                for (int h = 0; h < 2; h++) {
                    float2 xa[4], xb[4];
#pragma unroll
                    for (int nn = 0; nn < 4; nn++) {
                        int nt = h * 4 + nn;
                        xa[nn] = x2[(size_t)srcA * 32 + nt * 4 + tig];
                        xb[nn] = x2[(size_t)srcB * 32 + nt * 4 + tig];
                    }

                    float c[4][4];
#pragma unroll
                    for (int nn = 0; nn < 4; nn++)
#pragma unroll
                        for (int q = 0; q < 4; q++) c[nn][q] = 0.f;

#pragma unroll
                    for (int k8 = 0; k8 < 4; k8++) {
                        u32 a[4];
                        a[0] = sEa[w][buf][g][k8 * 8 + tig];
                        a[1] = sEa[w][buf][g + 8][k8 * 8 + tig];
                        a[2] = sEa[w][buf][g][k8 * 8 + 4 + tig];
                        a[3] = sEa[w][buf][g + 8][k8 * 8 + 4 + tig];
#pragma unroll
                        for (int nn = 0; nn < 4; nn++) {
                            int nt = h * 4 + nn;
                            u32 b[2];
                            *(uint2*)b = *(const uint2*)&sWf[((nt * 4 + k8) * 32 + lane) * 2];
                            mma_tf32(c[nn], a, b);
                        }
                    }

#pragma unroll
                    for (int nn = 0; nn < 4; nn++) {
                        int nt = h * 4 + nn;
                        float m0 = c[nn][0] + xa[nn].x + bp[nt].x;
                        float m1 = c[nn][1] + xa[nn].y + bp[nt].y;
                        float m2 = c[nn][2] + xb[nn].x + bp[nt].x;
                        float m3 = c[nn][3] + xb[nn].y + bp[nt].y;
                        m0 = fmaxf(m0, 0.f); m1 = fmaxf(m1, 0.f);
                        m2 = fmaxf(m2, 0.f); m3 = fmaxf(m3, 0.f);
                        if (!vA) { m0 = 0.f; m1 = 0.f; }
                        if (!vB) { m2 = 0.f; m3 = 0.f; }
                        float s0 = m0 + m2;
                        float s1 = m1 + m3;
                        s0 += __shfl_xor_sync(0xffffffffu, s0, 4);
                        s1 += __shfl_xor_sync(0xffffffffu, s1, 4);
                        s0 += __shfl_xor_sync(0xffffffffu, s0, 8);
                        s1 += __shfl_xor_sync(0xffffffffu, s1, 8);
                        s0 += __shfl_xor_sync(0xffffffffu, s0, 16);
                        s1 += __shfl_xor_sync(0xffffffffu, s1, 16);
                        accN[nt].x += s0;
                        accN[nt].y += s1;
                    }
                }

                // rotate
                prc = prn;
#pragma unroll
                for (int t = 0; t < 4; t++) ec[t] = en[t];
                buf ^= 1;
            }
        }
        *(float2*)&agg[(size_t)nd * 64 + g * 8 + tig * 2] = accN[g];
    }
}

// ---------------------------------------------------------------------------
// GEMM (n1): 128x128 block tile, 256 threads, 8x8 microtile via f32x2.
// ---------------------------------------------------------------------------
__device__ __forceinline__ void gemm_chunk128(
    const float* __restrict__ A, const float* __restrict__ Aadd, int lda4,
    const float* __restrict__ W, int k0, int m0,
    float (*sA)[36], float (*sW)[128], u64 acc2[8][4], int tid)
{
    const float4* A4  = (const float4*)A;
    const float4* Aa4 = (const float4*)Aadd;
#pragma unroll
    for (int it = 0; it < 4; ++it) {
        int idx = it * 256 + tid;
        int r   = idx >> 3;
        int cq  = idx & 7;
        float4 v = make_float4(0.f, 0.f, 0.f, 0.f);
        int gr = m0 + r;
        if (gr < N_NODES) {
            v = A4[(size_t)gr * lda4 + (k0 >> 2) + cq];
            if (Aadd) {
                float4 u = Aa4[(size_t)gr * lda4 + (k0 >> 2) + cq];
                v.x += u.x; v.y += u.y; v.z += u.z; v.w += u.w;
            }
        }
        *(float4*)&sA[r][cq * 4] = v;
    }
    const float4* W4 = (const float4*)W;
#pragma unroll
    for (int it = 0; it < 4; ++it) {
        int idx = it * 256 + tid;
        int kr  = idx >> 5;
        int cq  = idx & 31;
        *(float4*)&sW[kr][cq * 4] = W4[(size_t)(k0 + kr) * 32 + cq];
    }
    __syncthreads();

    const int rg = (tid >> 4) * 8;
    const int cg = (tid & 15) * 8;
#pragma unroll
    for (int kk = 0; kk < 32; kk += 2) {
        ulonglong2 b0a = *(const ulonglong2*)&sW[kk][cg];
        ulonglong2 b0b = *(const ulonglong2*)&sW[kk][cg + 4];
        ulonglong2 b1a = *(const ulonglong2*)&sW[kk + 1][cg];
        ulonglong2 b1b = *(const ulonglong2*)&sW[kk + 1][cg + 4];
        u64 bv0[4] = { b0a.x, b0a.y, b0b.x, b0b.y };
        u64 bv1[4] = { b1a.x, b1a.y, b1b.x, b1b.y };
#pragma unroll
        for (int i = 0; i < 8; i++) {
            float2 a2 = *(const float2*)&sA[rg + i][kk];
            u64 aP0 = pack2(a2.x, a2.x);
            u64 aP1 = pack2(a2.y, a2.y);
#pragma unroll
            for (int jp = 0; jp < 4; jp++) {
                acc2[i][jp] = ffma2(aP0, bv0[jp], acc2[i][jp]);
                acc2[i][jp] = ffma2(aP1, bv1[jp], acc2[i][jp]);
            }
        }
    }
    __syncthreads();
}

__device__ __forceinline__ float gelu_exact(float v) {
    return 0.5f * v * (1.f + erff(v * 0.70710678118654752f));
}

// ---------------------------------------------------------------------------
// N1: t[dir] = gelu((x + agg[dir]) @ W1 + b1)  (f32x2 — staging-bound)
// ---------------------------------------------------------------------------
__global__ __launch_bounds__(256, 2) void n1_kernel(
    const float* __restrict__ x,
    const float* __restrict__ W1_in,  const float* __restrict__ b1_in,
    const float* __restrict__ W1_out, const float* __restrict__ b1_out)
{
    const int dir = blockIdx.y;
    const float* W1 = dir ? W1_out : W1_in;
    const float* b1 = dir ? b1_out : b1_in;
    const float* agg = g_agg[dir];
    float* tptr = g_t[dir];

    __shared__ float sA[128][36];
    __shared__ float sW[32][128];
    u64 acc2[8][4];
#pragma unroll
    for (int i = 0; i < 8; i++)
#pragma unroll
        for (int j = 0; j < 4; j++) acc2[i][j] = 0ull;

    const int tid = threadIdx.x;
    const int m0  = blockIdx.x * 128;

    gemm_chunk128(x, agg, 16, W1,  0, m0, sA, sW, acc2, tid);
    gemm_chunk128(x, agg, 16, W1, 32, m0, sA, sW, acc2, tid);

    const int rg = (tid >> 4) * 8;
    const int cg = (tid & 15) * 8;
#pragma unroll
    for (int i = 0; i < 8; i++) {
        int gr = m0 + rg + i;
        if (gr < N_NODES) {
            float o[8];
#pragma unroll
            for (int jp = 0; jp < 4; jp++) {
                float lo, hi;
                unpack2(acc2[i][jp], lo, hi);
                o[2 * jp]     = gelu_exact(lo + b1[cg + 2 * jp]);
                o[2 * jp + 1] = gelu_exact(hi + b1[cg + 2 * jp + 1]);
            }
            *(float4*)&tptr[(size_t)gr * EMB + cg]     = *(float4*)&o[0];
            *(float4*)&tptr[(size_t)gr * EMB + cg + 4] = *(float4*)&o[4];
        }
    }
}

// ---------------------------------------------------------------------------
// N2 via tf32 mma.m16n8k8 (validated in R14).
// ---------------------------------------------------------------------------
__global__ __launch_bounds__(256, 2) void n2_kernel(
    const float* __restrict__ x,
    const float* __restrict__ W2_in,  const float* __restrict__ b2_in,
    const float* __restrict__ W2_out, const float* __restrict__ b2_out,
    const float* __restrict__ Wr,     const float* __restrict__ br,
    float* __restrict__ out)
{
    __shared__ u32 sAf[8 * 4 * 32 * 4];    // 16 KB
    __shared__ u32 sWf[16 * 4 * 32 * 2];   // 16 KB

    const int tid  = threadIdx.x;
    const int lane = tid & 31;
    const int warp = tid >> 5;
    const int mw   = warp >> 1;
    const int nw   = warp & 1;
    const int m0   = blockIdx.x * 128;

    float acc[2][8][4];
#pragma unroll
    for (int m = 0; m < 2; m++)
#pragma unroll
        for (int n = 0; n < 8; n++)
#pragma unroll
            for (int q = 0; q < 4; q++) acc[m][n][q] = 0.f;

#pragma unroll 1
    for (int c = 0; c < 10; c++) {
        const float4* A4; int lda4, k4b; const float4* W4; float scale;
        if (c < 4)      { A4 = (const float4*)g_t[1]; lda4 = 32; k4b = c * 8;
                          W4 = (const float4*)W2_out + (size_t)c * 32 * 32; scale = 0.5f; }
        else if (c < 8) { A4 = (const float4*)g_t[0]; lda4 = 32; k4b = (c - 4) * 8;
                          W4 = (const float4*)W2_in + (size_t)(c - 4) * 32 * 32; scale = 0.5f; }
        else            { A4 = (const float4*)x;      lda4 = 16; k4b = (c - 8) * 8;
                          W4 = (const float4*)Wr + (size_t)(c - 8) * 32 * 32; scale = 1.f; }

#pragma unroll
        for (int it = 0; it < 4; it++) {
            int idx = it * 256 + tid;
            int r   = idx >> 3;
            int q   = idx & 7;
            float4 v = make_float4(0.f, 0.f, 0.f, 0.f);
            int gr = m0 + r;
            if (gr < N_NODES) {
                v = A4[(size_t)gr * lda4 + k4b + q];
                v.x *= scale; v.y *= scale; v.z *= scale; v.w *= scale;
            }
            int mt = r >> 4, rr = r & 15;
            int gg = rr & 7, slr = rr >> 3;
            int k8 = q >> 1, slc = q & 1;
            int slot = slr + 2 * slc;
            u32* base = &sAf[(mt * 4 + k8) * 128 + gg * 4 * 4 + slot];
            base[0 * 4] = to_tf32(v.x);
            base[1 * 4] = to_tf32(v.y);
            base[2 * 4] = to_tf32(v.z);
            base[3 * 4] = to_tf32(v.w);
        }
#pragma unroll
        for (int it = 0; it < 4; it++) {
            int idx = it * 256 + tid;
            int kc  = idx >> 5;
            int n4  = idx & 31;
            float4 wv = W4[kc * 32 + n4];
            int k8 = kc >> 3, kk = kc & 7;
            int tg = kk & 3, slot = kk >> 2;
            float wf[4] = { wv.x, wv.y, wv.z, wv.w };
#pragma unroll
            for (int e = 0; e < 4; e++) {
                int n  = n4 * 4 + e;
                int nt = n >> 3, gg = n & 7;
                sWf[((nt * 4 + k8) * 32 + gg * 4 + tg) * 2 + slot] = to_tf32(wf[e]);
            }
        }
        __syncthreads();

#pragma unroll
        for (int k8 = 0; k8 < 4; k8++) {
            u32 af[2][4];
#pragma unroll
            for (int m = 0; m < 2; m++)
                *(uint4*)af[m] = *(const uint4*)&sAf[((mw * 2 + m) * 4 + k8) * 128 + lane * 4];
#pragma unroll
            for (int n = 0; n < 8; n++) {
                int nt = nw * 8 + n;
                u32 b[2];
                *(uint2*)b = *(const uint2*)&sWf[((nt * 4 + k8) * 32 + lane) * 2];
                mma_tf32(acc[0][n], af[0], b);
                mma_tf32(acc[1][n], af[1], b);
            }
        }
        __syncthreads();
    }

    const int gg  = lane >> 2;
    const int tg  = lane & 3;
#pragma unroll
    for (int m = 0; m < 2; m++) {
        int row  = m0 + (mw * 2 + m) * 16 + gg;
        int row2 = row + 8;
#pragma unroll
        for (int n = 0; n < 8; n++) {
            int col = nw * 64 + n * 8 + tg * 2;
            float bias0 = 0.5f * (b2_out[col] + b2_in[col]) + br[col];
            float bias1 = 0.5f * (b2_out[col + 1] + b2_in[col + 1]) + br[col + 1];
            if (row < N_NODES) {
                float2 o = make_float2(acc[m][n][0] + bias0, acc[m][n][1] + bias1);
                *(float2*)&out[(size_t)row * EMB + col] = o;
            }
            if (row2 < N_NODES) {
                float2 o = make_float2(acc[m][n][2] + bias0, acc[m][n][3] + bias1);
                *(float2*)&out[(size_t)row2 * EMB + col] = o;
            }
        }
    }
}

// ---------------------------------------------------------------------------
// launch
// ---------------------------------------------------------------------------
extern "C" void kernel_launch(void* const* d_in, const int* in_sizes, int n_in,
                              void* d_out, int out_size)
{
    const float* x      = (const float*)d_in[0];
    const int*   ei     = (const int*)d_in[1];
    const float* ea     = (const float*)d_in[2];
    const float* We_in  = (const float*)d_in[3];
    const float* be_in  = (const float*)d_in[4];
    const float* W1_in  = (const float*)d_in[5];
    const float* b1_in  = (const float*)d_in[6];
    const float* W2_in  = (const float*)d_in[7];
    const float* b2_in  = (const float*)d_in[8];
    const float* We_out = (const float*)d_in[9];
    const float* be_out = (const float*)d_in[10];
    const float* W1_out = (const float*)d_in[11];
    const float* b1_out = (const float*)d_in[12];
    const float* W2_out = (const float*)d_in[13];
    const float* b2_out = (const float*)d_in[14];
    const float* Wr     = (const float*)d_in[15];
    const float* br     = (const float*)d_in[16];
    float* out = (float*)d_out;

    // ---- CSR build ----
    zero_deg_kernel<<<(N_NODES + 255) / 256, 256>>>();
    count_kernel<<<(N_EDGES + 255) / 256, 256>>>(ei);
    scan1_kernel<<<dim3(NBLK, 2), SCAN_BLK>>>();
    scan2_kernel<<<dim3(1, 2), 256>>>();
    scan3_kernel<<<dim3(NBLK, 2), SCAN_BLK>>>();
    fill_kernel<<<(N_EDGES + 255) / 256, 256>>>(ei);

    // ---- aggregation (tf32 mma, pipelined) ----
    agg_kernel<<<dim3(296, 2), 256>>>(
        (const float2*)x, ea,
        We_in,  (const float2*)be_in,
        We_out, (const float2*)be_out);

    // ---- node MLPs ----
    dim3 ngrid((N_NODES + 127) / 128, 2);
    n1_kernel<<<ngrid, 256>>>(x, W1_in, b1_in, W1_out, b1_out);

    n2_kernel<<<(N_NODES + 127) / 128, 256>>>(
        x, W2_in, b2_in, W2_out, b2_out, Wr, br, out);
}